// round 1
// baseline (speedup 1.0000x reference)
#include <cuda_runtime.h>
#include <cstdint>

#define RR 100
#define BB 8
#define IWW 64
#define DD 128
#define BDD 32
#define OWW 16

// Scratch (allocation-free rule: __device__ globals)
__device__ float g_q[BB * RR * DD];     // [b][r][d]
__device__ float g_K[BB * RR * DD];     // [b][r][d]
__device__ float g_Vn[BB * RR * BDD];   // [b][r][bd]
__device__ float g_attn[BB * RR * RR];  // [b][s][t]  (relu'd raw logits)

// ---------------------------------------------------------------------------
// Kernel A: per-region embeddings. One CTA per region r, 128 threads (d),
// all 8 batches handled per CTA so every weight tile is read once per region.
// ---------------------------------------------------------------------------
__global__ __launch_bounds__(128) void kA(
    const float* __restrict__ x, const float* __restrict__ mean,
    const float* __restrict__ stddev,
    const float* __restrict__ kv_in_W, const float* __restrict__ kv_in_b,
    const float* __restrict__ kv_blk_W, const float* __restrict__ kv_blk_b,
    const float* __restrict__ q_in_W, const float* __restrict__ q_in_b,
    const float* __restrict__ q_blk_W, const float* __restrict__ q_blk_b,
    const float* __restrict__ key_W, const float* __restrict__ key_b,
    const float* __restrict__ value_W, const float* __restrict__ value_b)
{
    int r = blockIdx.x;
    int d = threadIdx.x;

    __shared__ float xn[BB][IWW];
    __shared__ float h1[BB][DD];
    __shared__ float kv2[BB][DD];

    float mu = mean[r];
    float isd = 1.0f / (stddev[r] + 1e-8f);
    for (int idx = d; idx < BB * IWW; idx += 128) {
        int b = idx / IWW, i = idx % IWW;
        xn[b][i] = (x[(b * RR + r) * IWW + i] - mu) * isd;
    }
    __syncthreads();

    float acc[BB];

    // ---- q path: Linear(IW->D) + ReLU ----
    {
        float bi = q_in_b[r * DD + d];
        #pragma unroll
        for (int b = 0; b < BB; b++) acc[b] = bi;
        const float* W = q_in_W + (size_t)r * IWW * DD + d;
        #pragma unroll 4
        for (int i = 0; i < IWW; i++) {
            float w = W[(size_t)i * DD];
            #pragma unroll
            for (int b = 0; b < BB; b++) acc[b] = fmaf(xn[b][i], w, acc[b]);
        }
        #pragma unroll
        for (int b = 0; b < BB; b++) h1[b][d] = fmaxf(acc[b], 0.0f);
        __syncthreads();
    }
    // ---- q path: Linear(D->D) -> g_q ----
    {
        float bi = q_blk_b[r * DD + d];
        #pragma unroll
        for (int b = 0; b < BB; b++) acc[b] = bi;
        const float* W = q_blk_W + (size_t)r * DD * DD + d;
        #pragma unroll 4
        for (int j = 0; j < DD; j++) {
            float w = W[(size_t)j * DD];
            #pragma unroll
            for (int b = 0; b < BB; b++) acc[b] = fmaf(h1[b][j], w, acc[b]);
        }
        #pragma unroll
        for (int b = 0; b < BB; b++) g_q[(b * RR + r) * DD + d] = acc[b];
        __syncthreads();  // h1 gets reused below
    }
    // ---- kv path: Linear(IW->D) + ReLU ----
    {
        float bi = kv_in_b[d];
        #pragma unroll
        for (int b = 0; b < BB; b++) acc[b] = bi;
        const float* W = kv_in_W + d;
        #pragma unroll 4
        for (int i = 0; i < IWW; i++) {
            float w = W[(size_t)i * DD];
            #pragma unroll
            for (int b = 0; b < BB; b++) acc[b] = fmaf(xn[b][i], w, acc[b]);
        }
        #pragma unroll
        for (int b = 0; b < BB; b++) h1[b][d] = fmaxf(acc[b], 0.0f);
        __syncthreads();
    }
    // ---- kv path: Linear(D->D) ----
    {
        float bi = kv_blk_b[d];
        #pragma unroll
        for (int b = 0; b < BB; b++) acc[b] = bi;
        const float* W = kv_blk_W + d;
        #pragma unroll 4
        for (int j = 0; j < DD; j++) {
            float w = W[(size_t)j * DD];
            #pragma unroll
            for (int b = 0; b < BB; b++) acc[b] = fmaf(h1[b][j], w, acc[b]);
        }
        #pragma unroll
        for (int b = 0; b < BB; b++) kv2[b][d] = acc[b];
        __syncthreads();
    }
    // ---- K = kv @ key_W + key_b -> g_K ----
    {
        float bi = key_b[d];
        #pragma unroll
        for (int b = 0; b < BB; b++) acc[b] = bi;
        const float* W = key_W + d;
        #pragma unroll 4
        for (int j = 0; j < DD; j++) {
            float w = W[(size_t)j * DD];
            #pragma unroll
            for (int b = 0; b < BB; b++) acc[b] = fmaf(kv2[b][j], w, acc[b]);
        }
        #pragma unroll
        for (int b = 0; b < BB; b++) g_K[(b * RR + r) * DD + d] = acc[b];
    }
    // ---- V = kv @ value_W + value_b; normalize -> g_Vn ----
    // warp w handles batches {w, w+4}; lane = bd
    {
        int w = d >> 5, lane = d & 31;
        #pragma unroll
        for (int h = 0; h < 2; h++) {
            int b = w + 4 * h;
            float v = value_b[lane];
            const float* W = value_W + lane;
            #pragma unroll 4
            for (int j = 0; j < DD; j++)
                v = fmaf(kv2[b][j], W[(size_t)j * BDD], v);
            float ss = v * v;
            #pragma unroll
            for (int o = 16; o > 0; o >>= 1) ss += __shfl_xor_sync(0xffffffffu, ss, o);
            float nrm = fmaxf(sqrtf(ss), 1e-12f);
            g_Vn[(b * RR + r) * BDD + lane] = v / nrm;
        }
    }
}

// ---------------------------------------------------------------------------
// Kernel B: attention logits. One CTA per (s,t) pair; streams the 64KB
// query_weight tile once (evict-first) and fuses bias + dot(K) + relu.
// ---------------------------------------------------------------------------
__global__ __launch_bounds__(128) void kB(
    const float* __restrict__ qw, const float* __restrict__ qb)
{
    int t = blockIdx.x;
    int s = blockIdx.y;
    int d = threadIdx.x;

    __shared__ float qs[BB][DD];
    __shared__ float sred[4][BB];

    #pragma unroll
    for (int b = 0; b < BB; b++) qs[b][d] = g_q[(b * RR + s) * DD + d];
    float k[BB];
    #pragma unroll
    for (int b = 0; b < BB; b++) k[b] = g_K[(b * RR + t) * DD + d];
    __syncthreads();

    float acc[BB];
    #pragma unroll
    for (int b = 0; b < BB; b++) acc[b] = 0.0f;

    const float* W = qw + ((size_t)(s * RR + t)) * DD * DD + d;
    #pragma unroll 4
    for (int i = 0; i < DD; i++) {
        float w = __ldcs(W + (size_t)i * DD);   // streaming, never reused
        #pragma unroll
        for (int b = 0; b < BB; b++) acc[b] = fmaf(qs[b][i], w, acc[b]);
    }
    float bias = __ldcs(qb + ((size_t)(s * RR + t)) * DD + d);

    #pragma unroll
    for (int b = 0; b < BB; b++) {
        float p = (acc[b] + bias) * k[b];
        #pragma unroll
        for (int o = 16; o > 0; o >>= 1) p += __shfl_xor_sync(0xffffffffu, p, o);
        if ((d & 31) == 0) sred[d >> 5][b] = p;
    }
    __syncthreads();
    if (d < BB) {
        float l = sred[0][d] + sred[1][d] + sred[2][d] + sred[3][d];
        g_attn[(d * RR + s) * RR + t] = fmaxf(l, 0.0f);
    }
}

// ---------------------------------------------------------------------------
// Kernel C: normalize attn, attn@Vn, reproj, post block, out proj, denorm.
// One CTA per region s, all 8 batches.
// ---------------------------------------------------------------------------
__global__ __launch_bounds__(128) void kC(
    const float* __restrict__ reproj_W, const float* __restrict__ reproj_b,
    const float* __restrict__ post_blk_W, const float* __restrict__ post_blk_b,
    const float* __restrict__ out_W, const float* __restrict__ out_b,
    const float* __restrict__ mean, const float* __restrict__ stddev,
    float* __restrict__ out)
{
    int s = blockIdx.x;
    int tid = threadIdx.x;

    __shared__ float at[BB][RR];
    __shared__ float ao[BB][BDD];
    __shared__ float ar[BB][DD];
    __shared__ float hs[BB][DD];
    __shared__ float inv[BB];

    for (int idx = tid; idx < BB * RR; idx += 128) {
        int b = idx / RR, t = idx % RR;
        at[b][t] = g_attn[(b * RR + s) * RR + t];
    }
    __syncthreads();
    if (tid < BB) {
        float sum = 0.0f;
        #pragma unroll 4
        for (int t = 0; t < RR; t++) sum += at[tid][t];
        inv[tid] = 1.0f / (1e-8f + sum);
    }
    __syncthreads();

    // att_out[b][bd] = (sum_t attn * Vn) * inv
    {
        int bd = tid & 31;
        int bh = tid >> 5;   // 0..3
        #pragma unroll
        for (int h = 0; h < 2; h++) {
            int b = bh + 4 * h;
            float a = 0.0f;
            const float* Vp = g_Vn + (size_t)(b * RR) * BDD + bd;
            #pragma unroll 4
            for (int t = 0; t < RR; t++)
                a = fmaf(at[b][t], Vp[(size_t)t * BDD], a);
            ao[b][bd] = a * inv[b];
        }
    }
    __syncthreads();

    int d = tid;
    float acc[BB];
    // reproj (BD->D) + relu
    {
        float rb = reproj_b[d];
        #pragma unroll
        for (int b = 0; b < BB; b++) acc[b] = rb;
        const float* W = reproj_W + d;
        #pragma unroll 4
        for (int j = 0; j < BDD; j++) {
            float w = W[(size_t)j * DD];
            #pragma unroll
            for (int b = 0; b < BB; b++) acc[b] = fmaf(ao[b][j], w, acc[b]);
        }
        #pragma unroll
        for (int b = 0; b < BB; b++) ar[b][d] = fmaxf(acc[b], 0.0f);
        __syncthreads();
    }
    // post block (D->D)
    {
        float pb = post_blk_b[s * DD + d];
        #pragma unroll
        for (int b = 0; b < BB; b++) acc[b] = pb;
        const float* W = post_blk_W + (size_t)s * DD * DD + d;
        #pragma unroll 4
        for (int j = 0; j < DD; j++) {
            float w = W[(size_t)j * DD];
            #pragma unroll
            for (int b = 0; b < BB; b++) acc[b] = fmaf(ar[b][j], w, acc[b]);
        }
        #pragma unroll
        for (int b = 0; b < BB; b++) hs[b][d] = acc[b];
        __syncthreads();
    }
    // output projection (D->OW) + denorm; 128 threads = 8 b x 16 o
    {
        int b = tid >> 4, o = tid & 15;
        float p = out_b[s * OWW + o];
        const float* W = out_W + (size_t)s * DD * OWW + o;
        #pragma unroll 4
        for (int j = 0; j < DD; j++)
            p = fmaf(hs[b][j], W[(size_t)j * OWW], p);
        out[(b * RR + s) * OWW + o] = p * stddev[s] + mean[s];
    }
}

extern "C" void kernel_launch(void* const* d_in, const int* in_sizes, int n_in,
                              void* d_out, int out_size)
{
    const float* x          = (const float*)d_in[0];
    const float* mean       = (const float*)d_in[1];
    const float* stddev     = (const float*)d_in[2];
    const float* kv_in_W    = (const float*)d_in[3];
    const float* kv_in_b    = (const float*)d_in[4];
    const float* kv_blk_W   = (const float*)d_in[5];
    const float* kv_blk_b   = (const float*)d_in[6];
    const float* q_in_W     = (const float*)d_in[7];
    const float* q_in_b     = (const float*)d_in[8];
    const float* q_blk_W    = (const float*)d_in[9];
    const float* q_blk_b    = (const float*)d_in[10];
    const float* key_W      = (const float*)d_in[11];
    const float* key_b      = (const float*)d_in[12];
    const float* value_W    = (const float*)d_in[13];
    const float* value_b    = (const float*)d_in[14];
    const float* qw         = (const float*)d_in[15];
    const float* qb         = (const float*)d_in[16];
    const float* reproj_W   = (const float*)d_in[17];
    const float* reproj_b   = (const float*)d_in[18];
    const float* post_blk_W = (const float*)d_in[19];
    const float* post_blk_b = (const float*)d_in[20];
    const float* out_W      = (const float*)d_in[21];
    const float* out_b      = (const float*)d_in[22];
    float* out = (float*)d_out;

    kA<<<RR, 128>>>(x, mean, stddev, kv_in_W, kv_in_b, kv_blk_W, kv_blk_b,
                    q_in_W, q_in_b, q_blk_W, q_blk_b,
                    key_W, key_b, value_W, value_b);
    kB<<<dim3(RR, RR), 128>>>(qw, qb);
    kC<<<RR, 128>>>(reproj_W, reproj_b, post_blk_W, post_blk_b,
                    out_W, out_b, mean, stddev, out);
}

// round 2
// speedup vs baseline: 1.0034x; 1.0034x over previous
#include <cuda_runtime.h>
#include <cstdint>

#define RR 100
#define BB 8
#define IWW 64
#define DD 128
#define BDD 32
#define OWW 16

// Scratch (allocation-free rule: __device__ globals)
__device__ float g_q[BB * RR * DD];     // [b][r][d]
__device__ float g_K[BB * RR * DD];     // [b][r][d]
__device__ float g_Vn[BB * RR * BDD];   // [b][r][bd]
__device__ float g_attn[BB * RR * RR];  // [b][s][t]  (relu'd raw logits)

// ---------------------------------------------------------------------------
// Kernel A: per-region embeddings, 3 independent paths per region:
//   path 0: q   = q_blk( relu( q_in(xn) ) )                 chain ~192 iters
//   path 1: kv  = kv_blk( relu( kv_in(xn) ) ); K = key(kv)  chain ~320 iters
//   path 2: kv  recomputed; V = value(kv); normalize        chain ~320 iters
// Deep unrolling (16) keeps ~16 loads in flight per warp to hide DRAM/L2
// latency at 1 warp/SMSP.
// ---------------------------------------------------------------------------
__global__ __launch_bounds__(128) void kA(
    const float* __restrict__ x, const float* __restrict__ mean,
    const float* __restrict__ stddev,
    const float* __restrict__ kv_in_W, const float* __restrict__ kv_in_b,
    const float* __restrict__ kv_blk_W, const float* __restrict__ kv_blk_b,
    const float* __restrict__ q_in_W, const float* __restrict__ q_in_b,
    const float* __restrict__ q_blk_W, const float* __restrict__ q_blk_b,
    const float* __restrict__ key_W, const float* __restrict__ key_b,
    const float* __restrict__ value_W, const float* __restrict__ value_b)
{
    int r = blockIdx.x;
    int path = blockIdx.y;
    int d = threadIdx.x;

    __shared__ float xn[BB][IWW];
    __shared__ float h1[BB][DD];
    __shared__ float kv2[BB][DD];

    float mu = mean[r];
    float isd = 1.0f / (stddev[r] + 1e-8f);
    for (int idx = d; idx < BB * IWW; idx += 128) {
        int b = idx / IWW, i = idx % IWW;
        xn[b][i] = (x[(b * RR + r) * IWW + i] - mu) * isd;
    }
    __syncthreads();

    float acc[BB];

    if (path == 0) {
        // ---- q path: Linear(IW->D) + ReLU ----
        {
            float bi = q_in_b[r * DD + d];
            #pragma unroll
            for (int b = 0; b < BB; b++) acc[b] = bi;
            const float* W = q_in_W + (size_t)r * IWW * DD + d;
            #pragma unroll 16
            for (int i = 0; i < IWW; i++) {
                float w = __ldg(W + (size_t)i * DD);
                #pragma unroll
                for (int b = 0; b < BB; b++) acc[b] = fmaf(xn[b][i], w, acc[b]);
            }
            #pragma unroll
            for (int b = 0; b < BB; b++) h1[b][d] = fmaxf(acc[b], 0.0f);
            __syncthreads();
        }
        // ---- q path: Linear(D->D) -> g_q ----
        {
            float bi = q_blk_b[r * DD + d];
            #pragma unroll
            for (int b = 0; b < BB; b++) acc[b] = bi;
            const float* W = q_blk_W + (size_t)r * DD * DD + d;
            #pragma unroll 16
            for (int j = 0; j < DD; j++) {
                float w = __ldg(W + (size_t)j * DD);
                #pragma unroll
                for (int b = 0; b < BB; b++) acc[b] = fmaf(h1[b][j], w, acc[b]);
            }
            #pragma unroll
            for (int b = 0; b < BB; b++) g_q[(b * RR + r) * DD + d] = acc[b];
        }
        return;
    }

    // paths 1 & 2 both need kv
    // ---- kv path: Linear(IW->D) + ReLU ----
    {
        float bi = kv_in_b[d];
        #pragma unroll
        for (int b = 0; b < BB; b++) acc[b] = bi;
        const float* W = kv_in_W + d;
        #pragma unroll 16
        for (int i = 0; i < IWW; i++) {
            float w = __ldg(W + (size_t)i * DD);
            #pragma unroll
            for (int b = 0; b < BB; b++) acc[b] = fmaf(xn[b][i], w, acc[b]);
        }
        #pragma unroll
        for (int b = 0; b < BB; b++) h1[b][d] = fmaxf(acc[b], 0.0f);
        __syncthreads();
    }
    // ---- kv path: Linear(D->D) ----
    {
        float bi = kv_blk_b[d];
        #pragma unroll
        for (int b = 0; b < BB; b++) acc[b] = bi;
        const float* W = kv_blk_W + d;
        #pragma unroll 16
        for (int j = 0; j < DD; j++) {
            float w = __ldg(W + (size_t)j * DD);
            #pragma unroll
            for (int b = 0; b < BB; b++) acc[b] = fmaf(h1[b][j], w, acc[b]);
        }
        #pragma unroll
        for (int b = 0; b < BB; b++) kv2[b][d] = acc[b];
        __syncthreads();
    }

    if (path == 1) {
        // ---- K = kv @ key_W + key_b -> g_K ----
        float bi = key_b[d];
        #pragma unroll
        for (int b = 0; b < BB; b++) acc[b] = bi;
        const float* W = key_W + d;
        #pragma unroll 16
        for (int j = 0; j < DD; j++) {
            float w = __ldg(W + (size_t)j * DD);
            #pragma unroll
            for (int b = 0; b < BB; b++) acc[b] = fmaf(kv2[b][j], w, acc[b]);
        }
        #pragma unroll
        for (int b = 0; b < BB; b++) g_K[(b * RR + r) * DD + d] = acc[b];
    } else {
        // ---- V = kv @ value_W + value_b; normalize -> g_Vn ----
        // warp w handles batches {w, w+4}; one weight load feeds both.
        int w = d >> 5, lane = d & 31;
        int b0 = w, b1 = w + 4;
        float v0 = value_b[lane];
        float v1 = v0;
        const float* W = value_W + lane;
        #pragma unroll 16
        for (int j = 0; j < DD; j++) {
            float wv = __ldg(W + (size_t)j * BDD);
            v0 = fmaf(kv2[b0][j], wv, v0);
            v1 = fmaf(kv2[b1][j], wv, v1);
        }
        float s0 = v0 * v0, s1 = v1 * v1;
        #pragma unroll
        for (int o = 16; o > 0; o >>= 1) {
            s0 += __shfl_xor_sync(0xffffffffu, s0, o);
            s1 += __shfl_xor_sync(0xffffffffu, s1, o);
        }
        g_Vn[(b0 * RR + r) * BDD + lane] = v0 / fmaxf(sqrtf(s0), 1e-12f);
        g_Vn[(b1 * RR + r) * BDD + lane] = v1 / fmaxf(sqrtf(s1), 1e-12f);
    }
}

// ---------------------------------------------------------------------------
// Kernel B: attention logits. One CTA per (s,t) pair; streams the 64KB
// query_weight tile once (evict-first) and fuses bias + dot(K) + relu.
// HBM-bound: 655 MB of query_weight streamed exactly once.
// ---------------------------------------------------------------------------
__global__ __launch_bounds__(128) void kB(
    const float* __restrict__ qw, const float* __restrict__ qb)
{
    int t = blockIdx.x;
    int s = blockIdx.y;
    int d = threadIdx.x;

    __shared__ float qs[BB][DD];
    __shared__ float sred[4][BB];

    #pragma unroll
    for (int b = 0; b < BB; b++) qs[b][d] = g_q[(b * RR + s) * DD + d];
    float k[BB];
    #pragma unroll
    for (int b = 0; b < BB; b++) k[b] = g_K[(b * RR + t) * DD + d];
    __syncthreads();

    float acc[BB];
    #pragma unroll
    for (int b = 0; b < BB; b++) acc[b] = 0.0f;

    const float* W = qw + ((size_t)(s * RR + t)) * DD * DD + d;
    #pragma unroll 8
    for (int i = 0; i < DD; i++) {
        float w = __ldcs(W + (size_t)i * DD);   // streaming, never reused
        #pragma unroll
        for (int b = 0; b < BB; b++) acc[b] = fmaf(qs[b][i], w, acc[b]);
    }
    float bias = __ldcs(qb + ((size_t)(s * RR + t)) * DD + d);

    #pragma unroll
    for (int b = 0; b < BB; b++) {
        float p = (acc[b] + bias) * k[b];
        #pragma unroll
        for (int o = 16; o > 0; o >>= 1) p += __shfl_xor_sync(0xffffffffu, p, o);
        if ((d & 31) == 0) sred[d >> 5][b] = p;
    }
    __syncthreads();
    if (d < BB) {
        float l = sred[0][d] + sred[1][d] + sred[2][d] + sred[3][d];
        g_attn[(d * RR + s) * RR + t] = fmaxf(l, 0.0f);
    }
}

// ---------------------------------------------------------------------------
// Kernel C: normalize attn, attn@Vn, reproj, post block, out proj, denorm.
// One CTA per region s, all 8 batches. Deep unroll for latency hiding.
// ---------------------------------------------------------------------------
__global__ __launch_bounds__(128) void kC(
    const float* __restrict__ reproj_W, const float* __restrict__ reproj_b,
    const float* __restrict__ post_blk_W, const float* __restrict__ post_blk_b,
    const float* __restrict__ out_W, const float* __restrict__ out_b,
    const float* __restrict__ mean, const float* __restrict__ stddev,
    float* __restrict__ out)
{
    int s = blockIdx.x;
    int tid = threadIdx.x;

    __shared__ float at[BB][RR];
    __shared__ float ao[BB][BDD];
    __shared__ float ar[BB][DD];
    __shared__ float hs[BB][DD];
    __shared__ float inv[BB];

    for (int idx = tid; idx < BB * RR; idx += 128) {
        int b = idx / RR, t = idx % RR;
        at[b][t] = g_attn[(b * RR + s) * RR + t];
    }
    __syncthreads();
    if (tid < BB) {
        float sum = 0.0f;
        #pragma unroll 10
        for (int t = 0; t < RR; t++) sum += at[tid][t];
        inv[tid] = 1.0f / (1e-8f + sum);
    }
    __syncthreads();

    // att_out[b][bd] = (sum_t attn * Vn) * inv
    {
        int bd = tid & 31;
        int bh = tid >> 5;   // 0..3
        int b0 = bh, b1 = bh + 4;
        float a0 = 0.0f, a1 = 0.0f;
        const float* V0 = g_Vn + (size_t)(b0 * RR) * BDD + bd;
        const float* V1 = g_Vn + (size_t)(b1 * RR) * BDD + bd;
        #pragma unroll 10
        for (int t = 0; t < RR; t++) {
            a0 = fmaf(at[b0][t], V0[(size_t)t * BDD], a0);
            a1 = fmaf(at[b1][t], V1[(size_t)t * BDD], a1);
        }
        ao[b0][bd] = a0 * inv[b0];
        ao[b1][bd] = a1 * inv[b1];
    }
    __syncthreads();

    int d = tid;
    float acc[BB];
    // reproj (BD->D) + relu
    {
        float rb = reproj_b[d];
        #pragma unroll
        for (int b = 0; b < BB; b++) acc[b] = rb;
        const float* W = reproj_W + d;
        #pragma unroll 16
        for (int j = 0; j < BDD; j++) {
            float w = __ldg(W + (size_t)j * DD);
            #pragma unroll
            for (int b = 0; b < BB; b++) acc[b] = fmaf(ao[b][j], w, acc[b]);
        }
        #pragma unroll
        for (int b = 0; b < BB; b++) ar[b][d] = fmaxf(acc[b], 0.0f);
        __syncthreads();
    }
    // post block (D->D)
    {
        float pb = post_blk_b[s * DD + d];
        #pragma unroll
        for (int b = 0; b < BB; b++) acc[b] = pb;
        const float* W = post_blk_W + (size_t)s * DD * DD + d;
        #pragma unroll 16
        for (int j = 0; j < DD; j++) {
            float w = __ldg(W + (size_t)j * DD);
            #pragma unroll
            for (int b = 0; b < BB; b++) acc[b] = fmaf(ar[b][j], w, acc[b]);
        }
        #pragma unroll
        for (int b = 0; b < BB; b++) hs[b][d] = acc[b];
        __syncthreads();
    }
    // output projection (D->OW) + denorm; 128 threads = 8 b x 16 o
    {
        int b = tid >> 4, o = tid & 15;
        float p = out_b[s * OWW + o];
        const float* W = out_W + (size_t)s * DD * OWW + o;
        #pragma unroll 16
        for (int j = 0; j < DD; j++)
            p = fmaf(hs[b][j], __ldg(W + (size_t)j * OWW), p);
        out[(b * RR + s) * OWW + o] = p * stddev[s] + mean[s];
    }
}

extern "C" void kernel_launch(void* const* d_in, const int* in_sizes, int n_in,
                              void* d_out, int out_size)
{
    const float* x          = (const float*)d_in[0];
    const float* mean       = (const float*)d_in[1];
    const float* stddev     = (const float*)d_in[2];
    const float* kv_in_W    = (const float*)d_in[3];
    const float* kv_in_b    = (const float*)d_in[4];
    const float* kv_blk_W   = (const float*)d_in[5];
    const float* kv_blk_b   = (const float*)d_in[6];
    const float* q_in_W     = (const float*)d_in[7];
    const float* q_in_b     = (const float*)d_in[8];
    const float* q_blk_W    = (const float*)d_in[9];
    const float* q_blk_b    = (const float*)d_in[10];
    const float* key_W      = (const float*)d_in[11];
    const float* key_b      = (const float*)d_in[12];
    const float* value_W    = (const float*)d_in[13];
    const float* value_b    = (const float*)d_in[14];
    const float* qw         = (const float*)d_in[15];
    const float* qb         = (const float*)d_in[16];
    const float* reproj_W   = (const float*)d_in[17];
    const float* reproj_b   = (const float*)d_in[18];
    const float* post_blk_W = (const float*)d_in[19];
    const float* post_blk_b = (const float*)d_in[20];
    const float* out_W      = (const float*)d_in[21];
    const float* out_b      = (const float*)d_in[22];
    float* out = (float*)d_out;

    kA<<<dim3(RR, 3), 128>>>(x, mean, stddev, kv_in_W, kv_in_b, kv_blk_W, kv_blk_b,
                             q_in_W, q_in_b, q_blk_W, q_blk_b,
                             key_W, key_b, value_W, value_b);
    kB<<<dim3(RR, RR), 128>>>(qw, qb);
    kC<<<RR, 128>>>(reproj_W, reproj_b, post_blk_W, post_blk_b,
                    out_W, out_b, mean, stddev, out);
}

// round 3
// speedup vs baseline: 1.2136x; 1.2095x over previous
#include <cuda_runtime.h>
#include <cstdint>

#define RR 100
#define BB 8
#define IWW 64
#define DD 128
#define BDD 32
#define OWW 16

typedef unsigned long long ull;

// ---- packed fp32x2 helpers (sm_103a FFMA2 path, PTX-only) ----
__device__ __forceinline__ ull pk2(float lo, float hi) {
    ull r; asm("mov.b64 %0,{%1,%2};" : "=l"(r) : "f"(lo), "f"(hi)); return r;
}
__device__ __forceinline__ void upk2(float& lo, float& hi, ull v) {
    asm("mov.b64 {%0,%1},%2;" : "=f"(lo), "=f"(hi) : "l"(v));
}
__device__ __forceinline__ ull fma2(ull a, ull b, ull c) {
    ull d; asm("fma.rn.f32x2 %0,%1,%2,%3;" : "=l"(d) : "l"(a), "l"(b), "l"(c)); return d;
}

// Scratch (allocation-free rule: __device__ globals)
__device__ float g_q[BB * RR * DD];     // [b][r][d]
__device__ float g_K[BB * RR * DD];     // [b][r][d]
__device__ float g_Vn[BB * RR * BDD];   // [b][r][bd]
__device__ float g_attn[BB * RR * RR];  // [b][s][t]  (relu'd raw logits)

// ---------------------------------------------------------------------------
// Kernel A: per-region embeddings. grid = (R, 3 paths, 2 batch-halves).
//   path 0: q   = q_blk( relu( q_in(xn) ) )
//   path 1: kv  = kv_blk( relu( kv_in(xn) ) ); K = key(kv)
//   path 2: kv  recomputed; V = value(kv); normalize
// 4 batches per CTA packed as 2 f32x2 pairs; FFMA2 halves FMA-pipe pressure.
// ---------------------------------------------------------------------------
__global__ __launch_bounds__(128) void kA(
    const float* __restrict__ x, const float* __restrict__ mean,
    const float* __restrict__ stddev,
    const float* __restrict__ kv_in_W, const float* __restrict__ kv_in_b,
    const float* __restrict__ kv_blk_W, const float* __restrict__ kv_blk_b,
    const float* __restrict__ q_in_W, const float* __restrict__ q_in_b,
    const float* __restrict__ q_blk_W, const float* __restrict__ q_blk_b,
    const float* __restrict__ key_W, const float* __restrict__ key_b,
    const float* __restrict__ value_W, const float* __restrict__ value_b)
{
    int r = blockIdx.x;
    int path = blockIdx.y;
    int bh = blockIdx.z;          // batch half: batches [4*bh, 4*bh+4)
    int d = threadIdx.x;

    __shared__ ull xn2[IWW][2];   // pair p packs batches (4bh+2p, 4bh+2p+1)
    __shared__ ull h2[DD][2];     // packed intermediate
    __shared__ float kvs[4][DD];  // scalar kv (for V path)

    float mu = mean[r];
    float isd = 1.0f / (stddev[r] + 1e-8f);
    // normalize + pack input: thread = (i, pair)
    {
        int i = d & 63, p = d >> 6;
        int b0 = 4 * bh + 2 * p;
        float a = (x[(b0 * RR + r) * IWW + i] - mu) * isd;
        float bb = (x[((b0 + 1) * RR + r) * IWW + i] - mu) * isd;
        xn2[i][p] = pk2(a, bb);
    }
    __syncthreads();

    ull acc2[2];

    if (path == 0) {
        // ---- Linear(IW->D) + ReLU ----
        {
            float bi = q_in_b[r * DD + d];
            acc2[0] = acc2[1] = pk2(bi, bi);
            const float* W = q_in_W + (size_t)r * IWW * DD + d;
            #pragma unroll 16
            for (int i = 0; i < IWW; i++) {
                float w = __ldg(W + (size_t)i * DD);
                ull w2 = pk2(w, w);
                acc2[0] = fma2(xn2[i][0], w2, acc2[0]);
                acc2[1] = fma2(xn2[i][1], w2, acc2[1]);
            }
            #pragma unroll
            for (int p = 0; p < 2; p++) {
                float lo, hi; upk2(lo, hi, acc2[p]);
                h2[d][p] = pk2(fmaxf(lo, 0.0f), fmaxf(hi, 0.0f));
            }
            __syncthreads();
        }
        // ---- Linear(D->D) -> g_q ----
        {
            float bi = q_blk_b[r * DD + d];
            acc2[0] = acc2[1] = pk2(bi, bi);
            const float* W = q_blk_W + (size_t)r * DD * DD + d;
            #pragma unroll 16
            for (int j = 0; j < DD; j++) {
                float w = __ldg(W + (size_t)j * DD);
                ull w2 = pk2(w, w);
                acc2[0] = fma2(h2[j][0], w2, acc2[0]);
                acc2[1] = fma2(h2[j][1], w2, acc2[1]);
            }
            #pragma unroll
            for (int p = 0; p < 2; p++) {
                float lo, hi; upk2(lo, hi, acc2[p]);
                int b0 = 4 * bh + 2 * p;
                g_q[(b0 * RR + r) * DD + d] = lo;
                g_q[((b0 + 1) * RR + r) * DD + d] = hi;
            }
        }
        return;
    }

    // paths 1 & 2: kv chain
    {
        float bi = kv_in_b[d];
        acc2[0] = acc2[1] = pk2(bi, bi);
        const float* W = kv_in_W + d;
        #pragma unroll 16
        for (int i = 0; i < IWW; i++) {
            float w = __ldg(W + (size_t)i * DD);
            ull w2 = pk2(w, w);
            acc2[0] = fma2(xn2[i][0], w2, acc2[0]);
            acc2[1] = fma2(xn2[i][1], w2, acc2[1]);
        }
        #pragma unroll
        for (int p = 0; p < 2; p++) {
            float lo, hi; upk2(lo, hi, acc2[p]);
            h2[d][p] = pk2(fmaxf(lo, 0.0f), fmaxf(hi, 0.0f));
        }
        __syncthreads();
    }
    {
        float bi = kv_blk_b[d];
        acc2[0] = acc2[1] = pk2(bi, bi);
        const float* W = kv_blk_W + d;
        #pragma unroll 16
        for (int j = 0; j < DD; j++) {
            float w = __ldg(W + (size_t)j * DD);
            ull w2 = pk2(w, w);
            acc2[0] = fma2(h2[j][0], w2, acc2[0]);
            acc2[1] = fma2(h2[j][1], w2, acc2[1]);
        }
        __syncthreads();   // h2 about to be overwritten
        #pragma unroll
        for (int p = 0; p < 2; p++) {
            float lo, hi; upk2(lo, hi, acc2[p]);
            h2[d][p] = pk2(lo, hi);
            if (path == 2) { kvs[2 * p][d] = lo; kvs[2 * p + 1][d] = hi; }
        }
        __syncthreads();
    }

    if (path == 1) {
        // ---- K = kv @ key_W + key_b -> g_K ----
        float bi = key_b[d];
        acc2[0] = acc2[1] = pk2(bi, bi);
        const float* W = key_W + d;
        #pragma unroll 16
        for (int j = 0; j < DD; j++) {
            float w = __ldg(W + (size_t)j * DD);
            ull w2 = pk2(w, w);
            acc2[0] = fma2(h2[j][0], w2, acc2[0]);
            acc2[1] = fma2(h2[j][1], w2, acc2[1]);
        }
        #pragma unroll
        for (int p = 0; p < 2; p++) {
            float lo, hi; upk2(lo, hi, acc2[p]);
            int b0 = 4 * bh + 2 * p;
            g_K[(b0 * RR + r) * DD + d] = lo;
            g_K[((b0 + 1) * RR + r) * DD + d] = hi;
        }
    } else {
        // ---- V = kv @ value_W + value_b; normalize -> g_Vn ----
        // warp w handles local batch w, lane = bd
        int w = d >> 5, lane = d & 31;
        float v = value_b[lane];
        const float* W = value_W + lane;
        #pragma unroll 16
        for (int j = 0; j < DD; j++)
            v = fmaf(kvs[w][j], __ldg(W + (size_t)j * BDD), v);
        float ss = v * v;
        #pragma unroll
        for (int o = 16; o > 0; o >>= 1) ss += __shfl_xor_sync(0xffffffffu, ss, o);
        int b = 4 * bh + w;
        g_Vn[(b * RR + r) * BDD + lane] = v / fmaxf(sqrtf(ss), 1e-12f);
    }
}

// ---------------------------------------------------------------------------
// Kernel B: attention logits. One CTA per (s,t); streams the 64KB W tile once
// (evict-first). 8 batches packed into 4 f32x2 pairs -> 4 FFMA2 per element
// instead of 8 FFMA; q pairs pre-packed in smem and read 2-at-a-time (LDS.128).
// ---------------------------------------------------------------------------
__global__ __launch_bounds__(128) void kB(
    const float* __restrict__ qw, const float* __restrict__ qb)
{
    int t = blockIdx.x;
    int s = blockIdx.y;
    int d = threadIdx.x;

    __shared__ __align__(16) ull qs2[DD][4];  // [i][pair]
    __shared__ float sred[4][BB];

    {
        float qv[BB];
        #pragma unroll
        for (int b = 0; b < BB; b++) qv[b] = g_q[(b * RR + s) * DD + d];
        #pragma unroll
        for (int p = 0; p < 4; p++) qs2[d][p] = pk2(qv[2 * p], qv[2 * p + 1]);
    }
    float k[BB];
    #pragma unroll
    for (int b = 0; b < BB; b++) k[b] = g_K[(b * RR + t) * DD + d];
    __syncthreads();

    ull acc2[4];
    #pragma unroll
    for (int p = 0; p < 4; p++) acc2[p] = pk2(0.0f, 0.0f);

    const float* W = qw + ((size_t)(s * RR + t)) * DD * DD + d;
    #pragma unroll 8
    for (int i = 0; i < DD; i++) {
        float w = __ldcs(W + (size_t)i * DD);   // streaming, never reused
        ull w2 = pk2(w, w);
        ulonglong2 qA = *reinterpret_cast<const ulonglong2*>(&qs2[i][0]);
        ulonglong2 qB = *reinterpret_cast<const ulonglong2*>(&qs2[i][2]);
        acc2[0] = fma2(qA.x, w2, acc2[0]);
        acc2[1] = fma2(qA.y, w2, acc2[1]);
        acc2[2] = fma2(qB.x, w2, acc2[2]);
        acc2[3] = fma2(qB.y, w2, acc2[3]);
    }
    float bias = __ldcs(qb + ((size_t)(s * RR + t)) * DD + d);

    float acc[BB];
    #pragma unroll
    for (int p = 0; p < 4; p++) upk2(acc[2 * p], acc[2 * p + 1], acc2[p]);

    #pragma unroll
    for (int b = 0; b < BB; b++) {
        float p = (acc[b] + bias) * k[b];
        #pragma unroll
        for (int o = 16; o > 0; o >>= 1) p += __shfl_xor_sync(0xffffffffu, p, o);
        if ((d & 31) == 0) sred[d >> 5][b] = p;
    }
    __syncthreads();
    if (d < BB) {
        float l = sred[0][d] + sred[1][d] + sred[2][d] + sred[3][d];
        g_attn[(d * RR + s) * RR + t] = fmaxf(l, 0.0f);
    }
}

// ---------------------------------------------------------------------------
// Kernel C: normalize attn, attn@Vn, reproj, post block, out proj, denorm.
// One CTA per region s, all 8 batches; post block uses packed FFMA2.
// ---------------------------------------------------------------------------
__global__ __launch_bounds__(128) void kC(
    const float* __restrict__ reproj_W, const float* __restrict__ reproj_b,
    const float* __restrict__ post_blk_W, const float* __restrict__ post_blk_b,
    const float* __restrict__ out_W, const float* __restrict__ out_b,
    const float* __restrict__ mean, const float* __restrict__ stddev,
    float* __restrict__ out)
{
    int s = blockIdx.x;
    int tid = threadIdx.x;

    __shared__ float at[BB][RR];
    __shared__ float ao[BB][BDD];
    __shared__ __align__(16) ull ar2[DD][4];
    __shared__ float hs[BB][DD];
    __shared__ float inv[BB];

    for (int idx = tid; idx < BB * RR; idx += 128) {
        int b = idx / RR, t = idx % RR;
        at[b][t] = g_attn[(b * RR + s) * RR + t];
    }
    __syncthreads();
    if (tid < BB) {
        float sum = 0.0f;
        #pragma unroll 10
        for (int t = 0; t < RR; t++) sum += at[tid][t];
        inv[tid] = 1.0f / (1e-8f + sum);
    }
    __syncthreads();

    // att_out[b][bd] = (sum_t attn * Vn) * inv
    {
        int bd = tid & 31;
        int bh = tid >> 5;
        int b0 = bh, b1 = bh + 4;
        float a0 = 0.0f, a1 = 0.0f;
        const float* V0 = g_Vn + (size_t)(b0 * RR) * BDD + bd;
        const float* V1 = g_Vn + (size_t)(b1 * RR) * BDD + bd;
        #pragma unroll 10
        for (int t = 0; t < RR; t++) {
            a0 = fmaf(at[b0][t], V0[(size_t)t * BDD], a0);
            a1 = fmaf(at[b1][t], V1[(size_t)t * BDD], a1);
        }
        ao[b0][bd] = a0 * inv[b0];
        ao[b1][bd] = a1 * inv[b1];
    }
    __syncthreads();

    int d = tid;
    // reproj (BD->D) + relu, packed result
    {
        float rb = reproj_b[d];
        float acc[BB];
        #pragma unroll
        for (int b = 0; b < BB; b++) acc[b] = rb;
        const float* W = reproj_W + d;
        #pragma unroll 16
        for (int j = 0; j < BDD; j++) {
            float w = __ldg(W + (size_t)j * DD);
            #pragma unroll
            for (int b = 0; b < BB; b++) acc[b] = fmaf(ao[b][j], w, acc[b]);
        }
        #pragma unroll
        for (int p = 0; p < 4; p++)
            ar2[d][p] = pk2(fmaxf(acc[2 * p], 0.0f), fmaxf(acc[2 * p + 1], 0.0f));
        __syncthreads();
    }
    // post block (D->D), packed
    {
        float pb = post_blk_b[s * DD + d];
        ull acc2[4];
        #pragma unroll
        for (int p = 0; p < 4; p++) acc2[p] = pk2(pb, pb);
        const float* W = post_blk_W + (size_t)s * DD * DD + d;
        #pragma unroll 16
        for (int j = 0; j < DD; j++) {
            float w = __ldg(W + (size_t)j * DD);
            ull w2 = pk2(w, w);
            ulonglong2 aA = *reinterpret_cast<const ulonglong2*>(&ar2[j][0]);
            ulonglong2 aB = *reinterpret_cast<const ulonglong2*>(&ar2[j][2]);
            acc2[0] = fma2(aA.x, w2, acc2[0]);
            acc2[1] = fma2(aA.y, w2, acc2[1]);
            acc2[2] = fma2(aB.x, w2, acc2[2]);
            acc2[3] = fma2(aB.y, w2, acc2[3]);
        }
        #pragma unroll
        for (int p = 0; p < 4; p++) {
            float lo, hi; upk2(lo, hi, acc2[p]);
            hs[2 * p][d] = lo; hs[2 * p + 1][d] = hi;
        }
        __syncthreads();
    }
    // output projection (D->OW) + denorm; 128 threads = 8 b x 16 o
    {
        int b = tid >> 4, o = tid & 15;
        float p = out_b[s * OWW + o];
        const float* W = out_W + (size_t)s * DD * OWW + o;
        #pragma unroll 16
        for (int j = 0; j < DD; j++)
            p = fmaf(hs[b][j], __ldg(W + (size_t)j * OWW), p);
        out[(b * RR + s) * OWW + o] = p * stddev[s] + mean[s];
    }
}

extern "C" void kernel_launch(void* const* d_in, const int* in_sizes, int n_in,
                              void* d_out, int out_size)
{
    const float* x          = (const float*)d_in[0];
    const float* mean       = (const float*)d_in[1];
    const float* stddev     = (const float*)d_in[2];
    const float* kv_in_W    = (const float*)d_in[3];
    const float* kv_in_b    = (const float*)d_in[4];
    const float* kv_blk_W   = (const float*)d_in[5];
    const float* kv_blk_b   = (const float*)d_in[6];
    const float* q_in_W     = (const float*)d_in[7];
    const float* q_in_b     = (const float*)d_in[8];
    const float* q_blk_W    = (const float*)d_in[9];
    const float* q_blk_b    = (const float*)d_in[10];
    const float* key_W      = (const float*)d_in[11];
    const float* key_b      = (const float*)d_in[12];
    const float* value_W    = (const float*)d_in[13];
    const float* value_b    = (const float*)d_in[14];
    const float* qw         = (const float*)d_in[15];
    const float* qb         = (const float*)d_in[16];
    const float* reproj_W   = (const float*)d_in[17];
    const float* reproj_b   = (const float*)d_in[18];
    const float* post_blk_W = (const float*)d_in[19];
    const float* post_blk_b = (const float*)d_in[20];
    const float* out_W      = (const float*)d_in[21];
    const float* out_b      = (const float*)d_in[22];
    float* out = (float*)d_out;

    kA<<<dim3(RR, 3, 2), 128>>>(x, mean, stddev, kv_in_W, kv_in_b, kv_blk_W, kv_blk_b,
                                q_in_W, q_in_b, q_blk_W, q_blk_b,
                                key_W, key_b, value_W, value_b);
    kB<<<dim3(RR, RR), 128>>>(qw, qb);
    kC<<<RR, 128>>>(reproj_W, reproj_b, post_blk_W, post_blk_b,
                    out_W, out_b, mean, stddev, out);
}

// round 4
// speedup vs baseline: 1.3252x; 1.0920x over previous
#include <cuda_runtime.h>
#include <cstdint>

#define RR 100
#define BB 8
#define IWW 64
#define DD 128
#define BDD 32
#define OWW 16

typedef unsigned long long ull;

// ---- packed fp32x2 helpers (sm_103a FFMA2 path, PTX-only) ----
__device__ __forceinline__ ull pk2(float lo, float hi) {
    ull r; asm("mov.b64 %0,{%1,%2};" : "=l"(r) : "f"(lo), "f"(hi)); return r;
}
__device__ __forceinline__ void upk2(float& lo, float& hi, ull v) {
    asm("mov.b64 {%0,%1},%2;" : "=f"(lo), "=f"(hi) : "l"(v));
}
__device__ __forceinline__ ull fma2(ull a, ull b, ull c) {
    ull d; asm("fma.rn.f32x2 %0,%1,%2,%3;" : "=l"(d) : "l"(a), "l"(b), "l"(c)); return d;
}
__device__ __forceinline__ ull add2(ull a, ull b) {
    ull d; asm("add.rn.f32x2 %0,%1,%2;" : "=l"(d) : "l"(a), "l"(b)); return d;
}

// Scratch (allocation-free rule: __device__ globals)
__device__ float g_q[BB * RR * DD];     // [b][r][d]
__device__ float g_K[BB * RR * DD];     // [b][r][d]
__device__ float g_Vn[BB * RR * BDD];   // [b][r][bd]
__device__ float g_attn[BB * RR * RR];  // [b][s][t]  (relu'd raw logits)

// Packed linear stage: acc2[2 pairs] += sum_i x2[i] * W[i*ldw]  (weight scalar
// broadcast to both slots). Loads batched 16-deep so 16 LDGs stay in flight.
template<int N>
__device__ __forceinline__ void lin2(ull acc2[2], const float* __restrict__ W,
                                     int ldw, const ull x2[][2]) {
    #pragma unroll
    for (int base = 0; base < N; base += 16) {
        float wb[16];
        #pragma unroll
        for (int u = 0; u < 16; u++) wb[u] = __ldg(W + (size_t)(base + u) * ldw);
        #pragma unroll
        for (int u = 0; u < 16; u++) {
            ull w2 = pk2(wb[u], wb[u]);
            acc2[0] = fma2(x2[base + u][0], w2, acc2[0]);
            acc2[1] = fma2(x2[base + u][1], w2, acc2[1]);
        }
    }
}

// ---------------------------------------------------------------------------
// Kernel A: per-region embeddings. grid = (R, 3 paths, 2 batch-halves).
// ---------------------------------------------------------------------------
__global__ __launch_bounds__(128) void kA(
    const float* __restrict__ x, const float* __restrict__ mean,
    const float* __restrict__ stddev,
    const float* __restrict__ kv_in_W, const float* __restrict__ kv_in_b,
    const float* __restrict__ kv_blk_W, const float* __restrict__ kv_blk_b,
    const float* __restrict__ q_in_W, const float* __restrict__ q_in_b,
    const float* __restrict__ q_blk_W, const float* __restrict__ q_blk_b,
    const float* __restrict__ key_W, const float* __restrict__ key_b,
    const float* __restrict__ value_W, const float* __restrict__ value_b)
{
    int r = blockIdx.x;
    int path = blockIdx.y;
    int bh = blockIdx.z;          // batch half: batches [4*bh, 4*bh+4)
    int d = threadIdx.x;

    __shared__ ull xn2[IWW][2];   // pair p packs batches (4bh+2p, 4bh+2p+1)
    __shared__ ull h2[DD][2];
    __shared__ float kvs[4][DD];  // scalar kv (for V path)

    float mu = mean[r];
    float isd = 1.0f / (stddev[r] + 1e-8f);
    {
        int i = d & 63, p = d >> 6;
        int b0 = 4 * bh + 2 * p;
        float a = (x[(b0 * RR + r) * IWW + i] - mu) * isd;
        float bb = (x[((b0 + 1) * RR + r) * IWW + i] - mu) * isd;
        xn2[i][p] = pk2(a, bb);
    }
    __syncthreads();

    ull acc2[2];

    if (path == 0) {
        {   // Linear(IW->D) + ReLU
            float bi = q_in_b[r * DD + d];
            acc2[0] = acc2[1] = pk2(bi, bi);
            lin2<IWW>(acc2, q_in_W + (size_t)r * IWW * DD + d, DD, xn2);
            #pragma unroll
            for (int p = 0; p < 2; p++) {
                float lo, hi; upk2(lo, hi, acc2[p]);
                h2[d][p] = pk2(fmaxf(lo, 0.0f), fmaxf(hi, 0.0f));
            }
            __syncthreads();
        }
        {   // Linear(D->D) -> g_q
            float bi = q_blk_b[r * DD + d];
            acc2[0] = acc2[1] = pk2(bi, bi);
            lin2<DD>(acc2, q_blk_W + (size_t)r * DD * DD + d, DD, h2);
            #pragma unroll
            for (int p = 0; p < 2; p++) {
                float lo, hi; upk2(lo, hi, acc2[p]);
                int b0 = 4 * bh + 2 * p;
                g_q[(b0 * RR + r) * DD + d] = lo;
                g_q[((b0 + 1) * RR + r) * DD + d] = hi;
            }
        }
        return;
    }

    // paths 1 & 2: kv chain
    {
        float bi = kv_in_b[d];
        acc2[0] = acc2[1] = pk2(bi, bi);
        lin2<IWW>(acc2, kv_in_W + d, DD, xn2);
        #pragma unroll
        for (int p = 0; p < 2; p++) {
            float lo, hi; upk2(lo, hi, acc2[p]);
            h2[d][p] = pk2(fmaxf(lo, 0.0f), fmaxf(hi, 0.0f));
        }
        __syncthreads();
    }
    {
        float bi = kv_blk_b[d];
        acc2[0] = acc2[1] = pk2(bi, bi);
        lin2<DD>(acc2, kv_blk_W + d, DD, h2);
        __syncthreads();   // h2 about to be overwritten
        #pragma unroll
        for (int p = 0; p < 2; p++) {
            float lo, hi; upk2(lo, hi, acc2[p]);
            h2[d][p] = pk2(lo, hi);
            if (path == 2) { kvs[2 * p][d] = lo; kvs[2 * p + 1][d] = hi; }
        }
        __syncthreads();
    }

    if (path == 1) {
        // ---- K = kv @ key_W + key_b -> g_K ----
        float bi = key_b[d];
        acc2[0] = acc2[1] = pk2(bi, bi);
        lin2<DD>(acc2, key_W + d, DD, h2);
        #pragma unroll
        for (int p = 0; p < 2; p++) {
            float lo, hi; upk2(lo, hi, acc2[p]);
            int b0 = 4 * bh + 2 * p;
            g_K[(b0 * RR + r) * DD + d] = lo;
            g_K[((b0 + 1) * RR + r) * DD + d] = hi;
        }
    } else {
        // ---- V = kv @ value_W + value_b; normalize -> g_Vn ----
        int w = d >> 5, lane = d & 31;
        float v = value_b[lane];
        const float* W = value_W + lane;
        #pragma unroll
        for (int base = 0; base < DD; base += 16) {
            float wb[16];
            #pragma unroll
            for (int u = 0; u < 16; u++) wb[u] = __ldg(W + (size_t)(base + u) * BDD);
            #pragma unroll
            for (int u = 0; u < 16; u++) v = fmaf(kvs[w][base + u], wb[u], v);
        }
        float ss = v * v;
        #pragma unroll
        for (int o = 16; o > 0; o >>= 1) ss += __shfl_xor_sync(0xffffffffu, ss, o);
        int b = 4 * bh + w;
        g_Vn[(b * RR + r) * BDD + lane] = v / fmaxf(sqrtf(ss), 1e-12f);
    }
}

// ---------------------------------------------------------------------------
// Kernel B: attention logits. One CTA per (s,t); streams the 64KB W tile with
// LDG.128 (thread owns 4 consecutive d-columns; warp owns a 32-row range).
// Partial sums per warp are dotted with K immediately (linear), reduced across
// warps via smem. bias term added by warp 0 only.
// ---------------------------------------------------------------------------
__global__ __launch_bounds__(128) void kB(
    const float* __restrict__ qw, const float* __restrict__ qb)
{
    int t = blockIdx.x;
    int s = blockIdx.y;
    int tid = threadIdx.x;
    int w = tid >> 5, lane = tid & 31;
    int dbase = 4 * lane;

    __shared__ __align__(16) ull q2[DD][4];  // [i][pair]: (b=2p, b=2p+1)
    __shared__ __align__(16) ull k2[DD][4];
    __shared__ float sred[4][BB];

    {
        int d = tid;
        float qv[BB], kv[BB];
        #pragma unroll
        for (int b = 0; b < BB; b++) {
            qv[b] = g_q[(b * RR + s) * DD + d];
            kv[b] = g_K[(b * RR + t) * DD + d];
        }
        #pragma unroll
        for (int p = 0; p < 4; p++) {
            q2[d][p] = pk2(qv[2 * p], qv[2 * p + 1]);
            k2[d][p] = pk2(kv[2 * p], kv[2 * p + 1]);
        }
    }
    __syncthreads();

    // acc2[c][p]: column dbase+c, batch pair p
    ull acc2[4][4];
    #pragma unroll
    for (int c = 0; c < 4; c++)
        #pragma unroll
        for (int p = 0; p < 4; p++) acc2[c][p] = 0ull;

    const float* W = qw + ((size_t)(s * RR + t)) * DD * DD + (size_t)w * 32 * DD + dbase;
    #pragma unroll
    for (int ii0 = 0; ii0 < 32; ii0 += 8) {
        float4 wv[8];
        #pragma unroll
        for (int u = 0; u < 8; u++)
            wv[u] = __ldcs(reinterpret_cast<const float4*>(W + (size_t)(ii0 + u) * DD));
        #pragma unroll
        for (int u = 0; u < 8; u++) {
            int i = w * 32 + ii0 + u;
            ulonglong2 qA = *reinterpret_cast<const ulonglong2*>(&q2[i][0]);
            ulonglong2 qB = *reinterpret_cast<const ulonglong2*>(&q2[i][2]);
            ull w0 = pk2(wv[u].x, wv[u].x);
            ull w1 = pk2(wv[u].y, wv[u].y);
            ull w2_ = pk2(wv[u].z, wv[u].z);
            ull w3 = pk2(wv[u].w, wv[u].w);
            acc2[0][0] = fma2(qA.x, w0, acc2[0][0]);
            acc2[0][1] = fma2(qA.y, w0, acc2[0][1]);
            acc2[0][2] = fma2(qB.x, w0, acc2[0][2]);
            acc2[0][3] = fma2(qB.y, w0, acc2[0][3]);
            acc2[1][0] = fma2(qA.x, w1, acc2[1][0]);
            acc2[1][1] = fma2(qA.y, w1, acc2[1][1]);
            acc2[1][2] = fma2(qB.x, w1, acc2[1][2]);
            acc2[1][3] = fma2(qB.y, w1, acc2[1][3]);
            acc2[2][0] = fma2(qA.x, w2_, acc2[2][0]);
            acc2[2][1] = fma2(qA.y, w2_, acc2[2][1]);
            acc2[2][2] = fma2(qB.x, w2_, acc2[2][2]);
            acc2[2][3] = fma2(qB.y, w2_, acc2[2][3]);
            acc2[3][0] = fma2(qA.x, w3, acc2[3][0]);
            acc2[3][1] = fma2(qA.y, w3, acc2[3][1]);
            acc2[3][2] = fma2(qB.x, w3, acc2[3][2]);
            acc2[3][3] = fma2(qB.y, w3, acc2[3][3]);
        }
    }

    // tail: dot partials with K (+ bias, warp 0 only), reduce.
    ull pp[4];
    #pragma unroll
    for (int p = 0; p < 4; p++) pp[p] = 0ull;
    float4 b4 = __ldcs(reinterpret_cast<const float4*>(
        qb + ((size_t)(s * RR + t)) * DD + dbase));
    float bias[4] = {b4.x, b4.y, b4.z, b4.w};
    #pragma unroll
    for (int c = 0; c < 4; c++) {
        int dd = dbase + c;
        #pragma unroll
        for (int p = 0; p < 4; p++) {
            ull a = acc2[c][p];
            if (w == 0) a = add2(a, pk2(bias[c], bias[c]));
            pp[p] = fma2(a, k2[dd][p], pp[p]);
        }
    }
    float pf[BB];
    #pragma unroll
    for (int p = 0; p < 4; p++) upk2(pf[2 * p], pf[2 * p + 1], pp[p]);
    #pragma unroll
    for (int b = 0; b < BB; b++) {
        #pragma unroll
        for (int o = 16; o > 0; o >>= 1)
            pf[b] += __shfl_xor_sync(0xffffffffu, pf[b], o);
    }
    if (lane == 0) {
        #pragma unroll
        for (int b = 0; b < BB; b++) sred[w][b] = pf[b];
    }
    __syncthreads();
    if (tid < BB) {
        float l = sred[0][tid] + sred[1][tid] + sred[2][tid] + sred[3][tid];
        g_attn[(tid * RR + s) * RR + t] = fmaxf(l, 0.0f);
    }
}

// ---------------------------------------------------------------------------
// Kernel C: normalize attn, attn@Vn, reproj, post block, out proj, denorm.
// ---------------------------------------------------------------------------
__global__ __launch_bounds__(128) void kC(
    const float* __restrict__ reproj_W, const float* __restrict__ reproj_b,
    const float* __restrict__ post_blk_W, const float* __restrict__ post_blk_b,
    const float* __restrict__ out_W, const float* __restrict__ out_b,
    const float* __restrict__ mean, const float* __restrict__ stddev,
    float* __restrict__ out)
{
    int s = blockIdx.x;
    int tid = threadIdx.x;

    __shared__ float at[BB][RR];
    __shared__ float ao[BB][BDD];
    __shared__ __align__(16) ull ar2[DD][4];
    __shared__ float hs[BB][DD];
    __shared__ float inv[BB];

    for (int idx = tid; idx < BB * RR; idx += 128) {
        int b = idx / RR, t = idx % RR;
        at[b][t] = g_attn[(b * RR + s) * RR + t];
    }
    __syncthreads();
    if (tid < BB) {
        float sum = 0.0f;
        #pragma unroll 10
        for (int t = 0; t < RR; t++) sum += at[tid][t];
        inv[tid] = 1.0f / (1e-8f + sum);
    }
    __syncthreads();

    {
        int bd = tid & 31;
        int bh = tid >> 5;
        int b0 = bh, b1 = bh + 4;
        float a0 = 0.0f, a1 = 0.0f;
        const float* V0 = g_Vn + (size_t)(b0 * RR) * BDD + bd;
        const float* V1 = g_Vn + (size_t)(b1 * RR) * BDD + bd;
        #pragma unroll 10
        for (int t = 0; t < RR; t++) {
            a0 = fmaf(at[b0][t], V0[(size_t)t * BDD], a0);
            a1 = fmaf(at[b1][t], V1[(size_t)t * BDD], a1);
        }
        ao[b0][bd] = a0 * inv[b0];
        ao[b1][bd] = a1 * inv[b1];
    }
    __syncthreads();

    int d = tid;
    // reproj (BD->D) + relu, packed result
    {
        float rb = reproj_b[d];
        float acc[BB];
        #pragma unroll
        for (int b = 0; b < BB; b++) acc[b] = rb;
        const float* W = reproj_W + d;
        #pragma unroll
        for (int base = 0; base < BDD; base += 16) {
            float wb[16];
            #pragma unroll
            for (int u = 0; u < 16; u++) wb[u] = __ldg(W + (size_t)(base + u) * DD);
            #pragma unroll
            for (int u = 0; u < 16; u++)
                #pragma unroll
                for (int b = 0; b < BB; b++) acc[b] = fmaf(ao[b][base + u], wb[u], acc[b]);
        }
        #pragma unroll
        for (int p = 0; p < 4; p++)
            ar2[d][p] = pk2(fmaxf(acc[2 * p], 0.0f), fmaxf(acc[2 * p + 1], 0.0f));
        __syncthreads();
    }
    // post block (D->D), packed, batched loads
    {
        float pb = post_blk_b[s * DD + d];
        ull acc2[4];
        #pragma unroll
        for (int p = 0; p < 4; p++) acc2[p] = pk2(pb, pb);
        const float* W = post_blk_W + (size_t)s * DD * DD + d;
        #pragma unroll
        for (int base = 0; base < DD; base += 16) {
            float wb[16];
            #pragma unroll
            for (int u = 0; u < 16; u++) wb[u] = __ldg(W + (size_t)(base + u) * DD);
            #pragma unroll
            for (int u = 0; u < 16; u++) {
                ull w2 = pk2(wb[u], wb[u]);
                ulonglong2 aA = *reinterpret_cast<const ulonglong2*>(&ar2[base + u][0]);
                ulonglong2 aB = *reinterpret_cast<const ulonglong2*>(&ar2[base + u][2]);
                acc2[0] = fma2(aA.x, w2, acc2[0]);
                acc2[1] = fma2(aA.y, w2, acc2[1]);
                acc2[2] = fma2(aB.x, w2, acc2[2]);
                acc2[3] = fma2(aB.y, w2, acc2[3]);
            }
        }
        #pragma unroll
        for (int p = 0; p < 4; p++) {
            float lo, hi; upk2(lo, hi, acc2[p]);
            hs[2 * p][d] = lo; hs[2 * p + 1][d] = hi;
        }
        __syncthreads();
    }
    // output projection (D->OW) + denorm; 128 threads = 8 b x 16 o
    {
        int b = tid >> 4, o = tid & 15;
        float p = out_b[s * OWW + o];
        const float* W = out_W + (size_t)s * DD * OWW + o;
        #pragma unroll
        for (int base = 0; base < DD; base += 16) {
            float wb[16];
            #pragma unroll
            for (int u = 0; u < 16; u++) wb[u] = __ldg(W + (size_t)(base + u) * OWW);
            #pragma unroll
            for (int u = 0; u < 16; u++) p = fmaf(hs[b][base + u], wb[u], p);
        }
        out[(b * RR + s) * OWW + o] = p * stddev[s] + mean[s];
    }
}

extern "C" void kernel_launch(void* const* d_in, const int* in_sizes, int n_in,
                              void* d_out, int out_size)
{
    const float* x          = (const float*)d_in[0];
    const float* mean       = (const float*)d_in[1];
    const float* stddev     = (const float*)d_in[2];
    const float* kv_in_W    = (const float*)d_in[3];
    const float* kv_in_b    = (const float*)d_in[4];
    const float* kv_blk_W   = (const float*)d_in[5];
    const float* kv_blk_b   = (const float*)d_in[6];
    const float* q_in_W     = (const float*)d_in[7];
    const float* q_in_b     = (const float*)d_in[8];
    const float* q_blk_W    = (const float*)d_in[9];
    const float* q_blk_b    = (const float*)d_in[10];
    const float* key_W      = (const float*)d_in[11];
    const float* key_b      = (const float*)d_in[12];
    const float* value_W    = (const float*)d_in[13];
    const float* value_b    = (const float*)d_in[14];
    const float* qw         = (const float*)d_in[15];
    const float* qb         = (const float*)d_in[16];
    const float* reproj_W   = (const float*)d_in[17];
    const float* reproj_b   = (const float*)d_in[18];
    const float* post_blk_W = (const float*)d_in[19];
    const float* post_blk_b = (const float*)d_in[20];
    const float* out_W      = (const float*)d_in[21];
    const float* out_b      = (const float*)d_in[22];
    float* out = (float*)d_out;

    kA<<<dim3(RR, 3, 2), 128>>>(x, mean, stddev, kv_in_W, kv_in_b, kv_blk_W, kv_blk_b,
                                q_in_W, q_in_b, q_blk_W, q_blk_b,
                                key_W, key_b, value_W, value_b);
    kB<<<dim3(RR, RR), 128>>>(qw, qb);
    kC<<<RR, 128>>>(reproj_W, reproj_b, post_blk_W, post_blk_b,
                    out_W, out_b, mean, stddev, out);
}